// round 17
// baseline (speedup 1.0000x reference)
#include <cuda_runtime.h>

// Problem constants (fixed shapes from reference setup_inputs)
#define BB 16
#define SS 64
#define II 128
#define HH 512
#define TT 5
#define H4 (HH / 4)       // 128 float4 lanes across H
#define NSL 32            // h-slices; each slice = 4 float4 = 16 floats
#define CH 16             // recurrence: s-steps per chunk

// ---------------------------------------------------------------------------
// Single fused kernel, no inter-CTA communication. CTA = (b, 16-wide h slice).
// R17: reshape 256x512 -> 512x256 (the R13-proven grid shape): 4 CTAs/SM,
// better SM balance (R16's 256-CTA grid left 40 SMs with a single CTA,
// costing ~6% DRAM throughput). Everything else keeps the R16 structure:
//   Phase 1: thread (s = tid>>2, h4c = tid&3) reduces over i=128, explicit
//   8-deep float4 load batches (MLP=8), 8KB enc slice in SMEM, x streamed
//   with .cs, cur -> SMEM (4KB, no global round-trip).
//   Phase 2: lanes 0-15 of warp 0 run the 16 LIF chains (lane = h), chunked
//   16-s register preloads, ~12-13cyc/step chain
//   (FFMA -> {FSETP || FADD} -> FSEL), z + coalesced STG off-path.
// ---------------------------------------------------------------------------
__global__ __launch_bounds__(256, 4)
void fused_kernel(const float* __restrict__ x,
                  const float* __restrict__ enc,
                  float* __restrict__ out) {
    __shared__ float4 senc4[II * 4];       // 128 i x 4 float4  = 8KB
    __shared__ float  scur[SS * 16];       // 64 s x 16 h       = 4KB

    const int tid = threadIdx.x;
    const int b   = blockIdx.x & 15;       // 0..15
    const int sl  = blockIdx.x >> 4;       // 0..31

    const float4* __restrict__ x4 = reinterpret_cast<const float4*>(x);
    const float4* __restrict__ e4 = reinterpret_cast<const float4*>(enc);

    // ---- stage encoding slice: 512 float4, 2 per thread ----
    #pragma unroll
    for (int idx = tid; idx < II * 4; idx += 256) {
        senc4[idx] = e4[(idx >> 2) * H4 + sl * 4 + (idx & 3)];
    }
    __syncthreads();

    // ---- phase 1: reduction over i, explicit MLP=8 batches ----
    {
        const int h4c = tid & 3;           // 0..3 within slice
        const int s   = tid >> 2;          // 0..63

        const float4* xp = x4 + ((long)(b * SS + s) * II) * H4 + sl * 4 + h4c;

        float4 acc = make_float4(0.f, 0.f, 0.f, 0.f);

        for (int i0 = 0; i0 < II; i0 += 8) {
            float4 xv[8];
            #pragma unroll
            for (int ii = 0; ii < 8; ii++)
                xv[ii] = __ldcs(xp + (i0 + ii) * H4);   // 8 LDGs in flight

            #pragma unroll
            for (int ii = 0; ii < 8; ii++) {
                const float4 ev = senc4[(i0 + ii) * 4 + h4c];
                acc.x = fmaf(xv[ii].x, ev.x, acc.x);
                acc.y = fmaf(xv[ii].y, ev.y, acc.y);
                acc.z = fmaf(xv[ii].z, ev.z, acc.z);
                acc.w = fmaf(xv[ii].w, ev.w, acc.w);
            }
        }
        reinterpret_cast<float4*>(scur)[s * 4 + h4c] = acc;
    }
    __syncthreads();

    // ---- phase 2: LIF recurrence, lanes 0-15 of warp 0 (lane = local h) ----
    if (tid < 16) {
        const int lane = tid;
        float* op = out + ((long)b * SS * TT) * HH + sl * 16 + lane;

        float v = 0.0f;
        for (int k = 0; k < SS / CH; k++) {
            float c[CH];
            #pragma unroll
            for (int j = 0; j < CH; j++)
                c[j] = scur[(k * CH + j) * 16 + lane];

            float* ok = op + (long)k * CH * TT * HH;
            #pragma unroll
            for (int s = 0; s < CH; s++) {
                const float cs = c[s];
                float* o = ok + s * TT * HH;
                #pragma unroll
                for (int t = 0; t < TT; t++) {
                    v = fmaf(0.9f, v, cs);           // v = ALPHA*v + i_t
                    const bool  p   = (v > 1.0f);    // FSETP
                    const float vm1 = v - 1.0f;      // FADD || FSETP
                    o[t * HH] = p ? 1.0f : 0.0f;     // z, off critical path
                    v = p ? vm1 : v;                 // FSEL
                }
            }
        }
    }
}

extern "C" void kernel_launch(void* const* d_in, const int* in_sizes, int n_in,
                              void* d_out, int out_size) {
    const float* x   = (const float*)d_in[0];   // [B,S,I,H] f32
    const float* enc = (const float*)d_in[1];   // [I,H] f32
    float* out = (float*)d_out;                 // [B, S*T, H] f32

    fused_kernel<<<BB * NSL, 256>>>(x, enc, out);   // 512 CTAs
}